// round 1
// baseline (speedup 1.0000x reference)
#include <cuda_runtime.h>
#include <math.h>
#include <stdint.h>

// Problem dims
#define B_    64
#define L_    1024
#define N_    64
#define INSZ  128
#define MEM   1024
#define DEC   3

// Scan kernel config
#define NCTA   128     // persistent CTAs (<=148 so all resident)
#define NT     512     // threads per CTA
#define JB     8       // state columns per CTA (128*8 = 1024)
#define KCHUNK 128     // h staging chunk (k dimension)
#define NCHUNK (MEM/KCHUNK)   // 8
#define KSPL   8       // per-thread K split
#define KPER   (KCHUNK/KSPL)  // 16

// ---------------- scratch (__device__ globals; no allocation allowed) ------
__device__ float g_inter[(size_t)L_ * B_ * INSZ];          // [l][b][k]   33 MB
__device__ float g_proj [(size_t)L_ * 3 * MEM * B_];       // [l][c][b]  805 MB
__device__ float g_h    [MEM * B_];                        // [k][b]     256 KB
__device__ float g_mem  [(size_t)L_ * MEM * B_];           // [l][k][b]  268 MB
__device__ unsigned int g_bar_count;
__device__ unsigned int g_bar_gen;

// ---------------- accurate, flag-independent activations -------------------
__device__ __forceinline__ float tanh_acc(float x) {
    float ax = fabsf(x);
    float e  = __expf(-2.0f * ax);
    float t  = (1.0f - e) / (1.0f + e);
    return copysignf(t, x);
}
__device__ __forceinline__ float sigmoid_acc(float z) {
    return 1.0f / (1.0f + __expf(-z));
}

// ---------------- reset (barrier state must be fresh every launch) ---------
__global__ void reset_kernel() {
    g_bar_count = 0u;
    g_bar_gen   = 0u;
}

// ---------------- K1a: inter[l][b][k] = x[b,l,:] @ W_sense + b_sense -------
__global__ void sense_kernel(const float* __restrict__ x,
                             const float* __restrict__ Ws,
                             const float* __restrict__ bs) {
    __shared__ float xs[N_];
    int bl = blockIdx.x;            // bl = b*L_ + l
    int b  = bl >> 10;
    int l  = bl & (L_ - 1);
    int t  = threadIdx.x;           // 128 threads, t = output k
    if (t < N_) xs[t] = x[(size_t)bl * N_ + t];
    __syncthreads();
    float acc = bs[t];
#pragma unroll 16
    for (int n = 0; n < N_; n++) acc += xs[n] * Ws[n * INSZ + t];
    g_inter[((size_t)l * B_ + b) * INSZ + t] = acc;
}

// ---------------- K1b: proj[l][c][b] = inter[l][b][:] @ W_im[:,c] ----------
// grid (L_, 24), 256 threads, dyn smem = 32KB (A^T) + 64KB (B) = 96KB
#define CB 128
__global__ void __launch_bounds__(256) proj_kernel(const float* __restrict__ Wim) {
    extern __shared__ float sm[];
    float* As = sm;                 // [k][b]  128x64
    float* Bs = sm + INSZ * B_;     // [k][c]  128x128
    int l  = blockIdx.x;
    int cb = blockIdx.y;
    int t  = threadIdx.x;

    for (int idx = t; idx < B_ * INSZ; idx += 256) {
        int b = idx >> 7, k = idx & 127;
        As[k * B_ + b] = g_inter[((size_t)l * B_ + b) * INSZ + k];
    }
    for (int idx = t; idx < INSZ * CB; idx += 256) {
        int k = idx >> 7, cc = idx & 127;
        Bs[k * CB + cc] = Wim[(size_t)k * (3 * MEM) + cb * CB + cc];
    }
    __syncthreads();

    int cg = t >> 3;        // 0..31 -> c0 = cg*4
    int bg = t & 7;         // 0..7  -> b0 = bg*8
    float acc[4][8];
#pragma unroll
    for (int i = 0; i < 4; i++)
#pragma unroll
        for (int j = 0; j < 8; j++) acc[i][j] = 0.0f;

    for (int k = 0; k < INSZ; k++) {
        float4 bv  = *(const float4*)&Bs[k * CB + cg * 4];
        float4 a0  = *(const float4*)&As[k * B_ + bg * 8];
        float4 a1  = *(const float4*)&As[k * B_ + bg * 8 + 4];
        float bb[4] = {bv.x, bv.y, bv.z, bv.w};
        float aa[8] = {a0.x, a0.y, a0.z, a0.w, a1.x, a1.y, a1.z, a1.w};
#pragma unroll
        for (int i = 0; i < 4; i++)
#pragma unroll
            for (int j = 0; j < 8; j++) acc[i][j] += bb[i] * aa[j];
    }

    size_t base = (size_t)l * (3 * MEM) * B_ + (size_t)(cb * CB) * B_;
#pragma unroll
    for (int i = 0; i < 4; i++) {
        size_t rb = base + (size_t)(cg * 4 + i) * B_ + bg * 8;
        *(float4*)&g_proj[rb]     = make_float4(acc[i][0], acc[i][1], acc[i][2], acc[i][3]);
        *(float4*)&g_proj[rb + 4] = make_float4(acc[i][4], acc[i][5], acc[i][6], acc[i][7]);
    }
}

// ---------------- grid barrier (all NCTA CTAs resident) --------------------
__device__ __forceinline__ void grid_barrier(unsigned int target) {
    __syncthreads();
    if (threadIdx.x == 0) {
        __threadfence();
        unsigned int tk = atomicAdd(&g_bar_count, 1u);
        if (tk == NCTA - 1) {
            atomicExch(&g_bar_count, 0u);
            __threadfence();
            atomicAdd(&g_bar_gen, 1u);
        } else {
            while (*(volatile unsigned int*)&g_bar_gen < target) { }
            __threadfence();
        }
    }
    __syncthreads();
}

// ---------------- K2: persistent recurrent scan ----------------------------
// smem: Wsm[1024][16] (64KB) + Hs[128][64] (32KB) + Red[8][64][16] (32KB) = 128KB
__global__ void __launch_bounds__(NT, 1) scan_kernel(const float* __restrict__ Wmm) {
    extern __shared__ float sm[];
    float* Wsm = sm;                      // k*16 + jj*2 + ac
    float* Hs  = sm + MEM * 16;           // [kk][b]
    float* Red = Hs + KCHUNK * B_;        // [ks][tile][16]

    int t  = threadIdx.x;
    int j0 = blockIdx.x * JB;

    // load W_mm slice: a-cols j0..j0+7 and c-cols 1024+j0..1024+j0+7, interleaved
    for (int idx = t; idx < MEM * 16; idx += NT) {
        int k = idx >> 4, r = idx & 15;
        int jj = r >> 1, ac = r & 1;
        Wsm[idx] = Wmm[(size_t)k * (2 * MEM) + ac * MEM + j0 + jj];
    }

    // GEMM role
    int b4 = (t & 15) * 4;          // 4 consecutive batches
    int jg = (t >> 4) & 3;          // column pair (2jg, 2jg+1)
    int ks = t >> 6;                // 0..7 K split
    // update role
    int ub = t & 63;
    int uj = t >> 6;                // 0..7

    float hreg = 0.0f;
    g_h[(j0 + uj) * B_ + ub] = 0.0f;
    __syncthreads();

    unsigned int bar = 0;
    grid_barrier(++bar);

    for (int l = 0; l < L_; l++) {
        float acc[16];
#pragma unroll
        for (int i = 0; i < 16; i++) acc[i] = 0.0f;

        for (int kc = 0; kc < NCHUNK; kc++) {
            __syncthreads();
            // stage h chunk (L2-fresh loads)
            const float4* src = (const float4*)(g_h + kc * KCHUNK * B_);
            float4* dst = (float4*)Hs;
#pragma unroll
            for (int idx = t; idx < KCHUNK * B_ / 4; idx += NT) dst[idx] = __ldcg(src + idx);
            __syncthreads();

            int kbase = ks * KPER;
#pragma unroll
            for (int kk = 0; kk < KPER; kk++) {
                int k = kbase + kk;
                float4 h4 = *(const float4*)&Hs[k * B_ + b4];
                float4 w4 = *(const float4*)&Wsm[(kc * KCHUNK + k) * 16 + jg * 4];
                // w4 = { a(2jg), c(2jg), a(2jg+1), c(2jg+1) }
                acc[0]  += h4.x * w4.x;  acc[1]  += h4.x * w4.y;
                acc[2]  += h4.x * w4.z;  acc[3]  += h4.x * w4.w;
                acc[4]  += h4.y * w4.x;  acc[5]  += h4.y * w4.y;
                acc[6]  += h4.y * w4.z;  acc[7]  += h4.y * w4.w;
                acc[8]  += h4.z * w4.x;  acc[9]  += h4.z * w4.y;
                acc[10] += h4.z * w4.z;  acc[11] += h4.z * w4.w;
                acc[12] += h4.w * w4.x;  acc[13] += h4.w * w4.y;
                acc[14] += h4.w * w4.z;  acc[15] += h4.w * w4.w;
            }
        }

        __syncthreads();
        {
            int tile = (t & 15) * 4 + jg;
            float* rp = &Red[(ks * 64 + tile) * 16];
#pragma unroll
            for (int i = 0; i < 16; i++) rp[i] = acc[i];
        }
        __syncthreads();

        // elementwise nBRC update: thread (b=ub, jj=uj)
        {
            int b = ub, jj = uj;
            int tl  = (b >> 2) * 4 + (jj >> 1);
            int off = ((b & 3) * 2 + (jj & 1)) * 2;
            float ma = 0.0f, mc = 0.0f;
#pragma unroll
            for (int s = 0; s < KSPL; s++) {
                ma += Red[(s * 64 + tl) * 16 + off];
                mc += Red[(s * 64 + tl) * 16 + off + 1];
            }
            int j = j0 + jj;
            size_t pb = (size_t)l * (3 * MEM) * B_;
            float ia = g_proj[pb + (size_t)j * B_ + b];
            float ic = g_proj[pb + (size_t)(MEM + j) * B_ + b];
            float io = g_proj[pb + (size_t)(2 * MEM + j) * B_ + b];

            float a  = 1.0f + tanh_acc(ia + ma);
            float c  = sigmoid_acc(ic + mc);
            float hn = c * hreg + (1.0f - c) * tanh_acc(io + a * hreg);
            hreg = hn;
            g_h[j * B_ + b] = hn;
            g_mem[(size_t)l * MEM * B_ + (size_t)j * B_ + b] = hn;
        }
        grid_barrier(++bar);
    }
}

// ---------------- K3: logits + softmax -------------------------------------
__global__ void logits_kernel(const float* __restrict__ Wact,
                              const float* __restrict__ bact,
                              float* __restrict__ out) {
    __shared__ float Wa[MEM * DEC];
    int l = blockIdx.x;
    int b = threadIdx.x;    // 64 threads
    for (int idx = b; idx < MEM * DEC; idx += B_) Wa[idx] = Wact[idx];
    __syncthreads();

    float a0 = bact[0], a1 = bact[1], a2 = bact[2];
    const float* mp = g_mem + (size_t)l * MEM * B_ + b;
#pragma unroll 8
    for (int k = 0; k < MEM; k++) {
        float v = mp[(size_t)k * B_];
        a0 += v * Wa[k * 3 + 0];
        a1 += v * Wa[k * 3 + 1];
        a2 += v * Wa[k * 3 + 2];
    }
    float m  = fmaxf(a0, fmaxf(a1, a2));
    float e0 = __expf(a0 - m), e1 = __expf(a1 - m), e2 = __expf(a2 - m);
    float inv = 1.0f / (e0 + e1 + e2);
    size_t ob = ((size_t)b * L_ + l) * DEC;
    out[ob + 0] = e0 * inv;
    out[ob + 1] = e1 * inv;
    out[ob + 2] = e2 * inv;
}

// ---------------- launch ----------------------------------------------------
extern "C" void kernel_launch(void* const* d_in, const int* in_sizes, int n_in,
                              void* d_out, int out_size) {
    (void)in_sizes; (void)n_in; (void)out_size;
    const float* x   = (const float*)d_in[0];
    const float* Ws  = (const float*)d_in[1];
    const float* bs  = (const float*)d_in[2];
    const float* Wim = (const float*)d_in[3];
    const float* Wmm = (const float*)d_in[4];
    const float* Wac = (const float*)d_in[5];
    const float* bac = (const float*)d_in[6];
    float* out = (float*)d_out;

    cudaFuncSetAttribute(proj_kernel, cudaFuncAttributeMaxDynamicSharedMemorySize, 98304);
    cudaFuncSetAttribute(scan_kernel, cudaFuncAttributeMaxDynamicSharedMemorySize, 131072);

    reset_kernel<<<1, 1>>>();
    sense_kernel<<<B_ * L_, 128>>>(x, Ws, bs);
    proj_kernel<<<dim3(L_, 24), 256, 98304>>>(Wim);
    scan_kernel<<<NCTA, NT, 131072>>>(Wmm);
    logits_kernel<<<L_, B_>>>(Wac, bac, out);
}

// round 4
// speedup vs baseline: 1.5140x; 1.5140x over previous
#include <cuda.h>
#include <cuda_runtime.h>
#include <cuda_bf16.h>
#include <math.h>
#include <stdint.h>

// Problem dims
#define B_    64
#define L_    1024
#define N_    64
#define INSZ  128
#define MEM   1024
#define DEC   3

#define NCTA  128
#define NT    512
#define JB    8

// ---------------- scratch ----------------------------------------------------
__device__ float g_inter[(size_t)L_ * B_ * INSZ];
__device__ float g_proj [(size_t)L_ * 3 * MEM * B_];          // [l][col][b]
__device__ __nv_bfloat16 g_hsplit[128 * MEM];                 // rows 0-63 hi, 64-127 lo
__device__ float g_mem  [(size_t)L_ * MEM * B_];              // [l][j][b]
__device__ unsigned int g_bar_count;
__device__ unsigned int g_bar_gen;

// ---------------- PTX helpers ------------------------------------------------
__device__ __forceinline__ uint32_t smem_u32(const void* p) {
    uint32_t a;
    asm("{ .reg .u64 t; cvta.to.shared.u64 t, %1; cvt.u32.u64 %0, t; }" : "=r"(a) : "l"(p));
    return a;
}
__device__ __forceinline__ uint32_t ctarank() {
    uint32_t r; asm("mov.u32 %0, %%cluster_ctarank;" : "=r"(r)); return r;
}

#define MBAR_INIT(a, c) asm volatile("mbarrier.init.shared.b64 [%0], %1;" :: "r"((uint32_t)(a)), "r"((uint32_t)(c)) : "memory")
#define MBAR_EXPECT_TX(a, n) asm volatile("mbarrier.arrive.expect_tx.shared.b64 _, [%0], %1;" :: "r"((uint32_t)(a)), "r"((uint32_t)(n)) : "memory")

#define MBAR_WAIT(a, par) do { \
    uint32_t _m = (uint32_t)(a); uint32_t _p = (uint32_t)(par); uint32_t _d; \
    asm volatile("{\n\t.reg .pred p;\n\t" \
        "mbarrier.try_wait.parity.acquire.cta.shared::cta.b64 p, [%1], %2;\n\t" \
        "selp.b32 %0, 1, 0, p;\n\t}" : "=r"(_d) : "r"(_m), "r"(_p) : "memory"); \
    if (!_d) { \
        asm volatile("{\n\t.reg .pred P1;\n\tWL_%=:\n\t" \
            "mbarrier.try_wait.parity.acquire.cta.shared::cta.b64 P1, [%0], %1, 0x989680;\n\t" \
            "@P1 bra.uni WD_%=;\n\tbra.uni WL_%=;\n\tWD_%=:\n\t}" \
            :: "r"(_m), "r"(_p) : "memory"); \
    } } while (0)

#define TMA_MC(dst, tm, cx, cy, cz, mbar, mask) \
    asm volatile("cp.async.bulk.tensor.3d.shared::cluster.global.tile.mbarrier::complete_tx::bytes.multicast::cluster " \
        "[%0], [%1, {%2, %3, %4}], [%5], %6;" \
        :: "r"((uint32_t)(dst)), "l"(tm), "r"((int32_t)(cx)), "r"((int32_t)(cy)), "r"((int32_t)(cz)), \
           "r"((uint32_t)(mbar)), "h"((uint16_t)(mask)) : "memory")

#define FENCE_ASYNC_ALL() asm volatile("fence.proxy.async;" ::: "memory")
#define CLUSTER_SYNC() do { \
    asm volatile("barrier.cluster.arrive.aligned;" ::: "memory"); \
    asm volatile("barrier.cluster.wait.aligned;" ::: "memory"); } while (0)

__device__ __forceinline__ void ldmatrix4(uint32_t& a0, uint32_t& a1, uint32_t& a2, uint32_t& a3,
                                          uint32_t addr) {
    asm volatile("ldmatrix.sync.aligned.m8n8.x4.shared.b16 {%0,%1,%2,%3}, [%4];"
        : "=r"(a0), "=r"(a1), "=r"(a2), "=r"(a3) : "r"(addr));
}
__device__ __forceinline__ void mma16816(float* d, uint32_t a0, uint32_t a1, uint32_t a2, uint32_t a3,
                                         uint32_t b0, uint32_t b1) {
    asm volatile("mma.sync.aligned.m16n8k16.row.col.f32.bf16.bf16.f32 "
        "{%0,%1,%2,%3}, {%4,%5,%6,%7}, {%8,%9}, {%0,%1,%2,%3};"
        : "+f"(d[0]), "+f"(d[1]), "+f"(d[2]), "+f"(d[3])
        : "r"(a0), "r"(a1), "r"(a2), "r"(a3), "r"(b0), "r"(b1));
}

// ---------------- activations ------------------------------------------------
__device__ __forceinline__ float tanh_acc(float x) {
    float ax = fabsf(x);
    float e  = __expf(-2.0f * ax);
    float t  = (1.0f - e) / (1.0f + e);
    return copysignf(t, x);
}
__device__ __forceinline__ float sigmoid_acc(float z) {
    return 1.0f / (1.0f + __expf(-z));
}
__device__ __forceinline__ uint32_t packbf(float x, float y, bool lo) {
    __nv_bfloat16 xh = __float2bfloat16(x), yh = __float2bfloat16(y);
    if (lo) {
        xh = __float2bfloat16(x - __bfloat162float(xh));
        yh = __float2bfloat16(y - __bfloat162float(yh));
    }
    return ((uint32_t)__bfloat16_as_ushort(yh) << 16) | (uint32_t)__bfloat16_as_ushort(xh);
}

// ---------------- reset -------------------------------------------------------
__global__ void reset_kernel() { g_bar_count = 0u; g_bar_gen = 0u; }

// ---------------- K1a: sense --------------------------------------------------
__global__ void sense_kernel(const float* __restrict__ x,
                             const float* __restrict__ Ws,
                             const float* __restrict__ bs) {
    __shared__ float xs[N_];
    int bl = blockIdx.x;
    int b  = bl >> 10;
    int l  = bl & (L_ - 1);
    int t  = threadIdx.x;
    if (t < N_) xs[t] = x[(size_t)bl * N_ + t];
    __syncthreads();
    float acc = bs[t];
#pragma unroll 16
    for (int n = 0; n < N_; n++) acc += xs[n] * Ws[n * INSZ + t];
    g_inter[((size_t)l * B_ + b) * INSZ + t] = acc;
}

// ---------------- K1b: proj ---------------------------------------------------
#define CB 128
__global__ void __launch_bounds__(256) proj_kernel(const float* __restrict__ Wim) {
    extern __shared__ float sm[];
    float* As = sm;
    float* Bs = sm + INSZ * B_;
    int l  = blockIdx.x;
    int cb = blockIdx.y;
    int t  = threadIdx.x;

    for (int idx = t; idx < B_ * INSZ; idx += 256) {
        int b = idx >> 7, k = idx & 127;
        As[k * B_ + b] = g_inter[((size_t)l * B_ + b) * INSZ + k];
    }
    for (int idx = t; idx < INSZ * CB; idx += 256) {
        int k = idx >> 7, cc = idx & 127;
        Bs[k * CB + cc] = Wim[(size_t)k * (3 * MEM) + cb * CB + cc];
    }
    __syncthreads();

    int cg = t >> 3;
    int bg = t & 7;
    float acc[4][8];
#pragma unroll
    for (int i = 0; i < 4; i++)
#pragma unroll
        for (int j = 0; j < 8; j++) acc[i][j] = 0.0f;

    for (int k = 0; k < INSZ; k++) {
        float4 bv  = *(const float4*)&Bs[k * CB + cg * 4];
        float4 a0  = *(const float4*)&As[k * B_ + bg * 8];
        float4 a1  = *(const float4*)&As[k * B_ + bg * 8 + 4];
        float bb[4] = {bv.x, bv.y, bv.z, bv.w};
        float aa[8] = {a0.x, a0.y, a0.z, a0.w, a1.x, a1.y, a1.z, a1.w};
#pragma unroll
        for (int i = 0; i < 4; i++)
#pragma unroll
            for (int j = 0; j < 8; j++) acc[i][j] += bb[i] * aa[j];
    }

    size_t base = (size_t)l * (3 * MEM) * B_ + (size_t)(cb * CB) * B_;
#pragma unroll
    for (int i = 0; i < 4; i++) {
        size_t rb = base + (size_t)(cg * 4 + i) * B_ + bg * 8;
        *(float4*)&g_proj[rb]     = make_float4(acc[i][0], acc[i][1], acc[i][2], acc[i][3]);
        *(float4*)&g_proj[rb + 4] = make_float4(acc[i][4], acc[i][5], acc[i][6], acc[i][7]);
    }
}

// ---------------- grid barrier -----------------------------------------------
__device__ __forceinline__ void grid_barrier(unsigned int target) {
    __syncthreads();
    if (threadIdx.x == 0) {
        __threadfence();
        unsigned int tk = atomicAdd(&g_bar_count, 1u);
        if (tk == NCTA - 1) {
            atomicExch(&g_bar_count, 0u);
            __threadfence();
            atomicAdd(&g_bar_gen, 1u);
        } else {
            while (*(volatile unsigned int*)&g_bar_gen < target) { }
            __threadfence();
        }
    }
    __syncthreads();
}

// ---------------- K2: mma.sync tensor-core scan --------------------------------
// smem: [0,1024) mbarriers; [1024,+64K) W frags; [66560,+128K) A bufs; Red 128x33
#define OFF_FULL0  0
#define OFF_FULL1  8
#define OFF_W      1024
#define OFF_A      (OFF_W + 65536)
#define OFF_RED    (OFF_A + 131072)
#define SMEM_SCAN  (OFF_RED + 128 * 33 * 4)

__global__ void __launch_bounds__(NT, 1) __cluster_dims__(4, 1, 1)
scan_tc(const float* __restrict__ Wmm, const __grid_constant__ CUtensorMap tmap) {
    extern __shared__ char smem[];
    uint32_t sb = smem_u32(smem);
    float* RED = (float*)(smem + OFF_RED);
    uint2* Wsm = (uint2*)(smem + OFF_W);
    int t    = threadIdx.x;
    int wid  = t >> 5, lane = t & 31;
    int j0   = blockIdx.x * JB;
    uint32_t rank = ctarank();

    if (t == 0) {
        MBAR_INIT(sb + OFF_FULL0, 1);
        MBAR_INIT(sb + OFF_FULL1, 1);
    }

    // ---- resident W fragments: Wsm[(gk*4 + nt)*32 + lane] = uint2{b0,b1}
    // n_local = nt*8 + lane/4; grp 0:a_hi 1:c_hi 2:a_lo 3:c_lo; k0 = gk*16 + (lane%4)*2
    for (int idx = t; idx < 64 * 4 * 32; idx += NT) {
        int ln = idx & 31, nt = (idx >> 5) & 3, gk = idx >> 7;
        int n_local = nt * 8 + (ln >> 2);
        int grp = n_local >> 3, jj = n_local & 7;
        int col = ((grp & 1) ? MEM : 0) + j0 + jj;
        bool lo = (grp >= 2);
        int k0 = gk * 16 + (ln & 3) * 2;
        float w0 = Wmm[(size_t)k0 * (2 * MEM) + col];
        float w1 = Wmm[(size_t)(k0 + 1) * (2 * MEM) + col];
        float w8 = Wmm[(size_t)(k0 + 8) * (2 * MEM) + col];
        float w9 = Wmm[(size_t)(k0 + 9) * (2 * MEM) + col];
        Wsm[idx] = make_uint2(packbf(w0, w1, lo), packbf(w8, w9, lo));
    }

    // ---- init h = 0
    int b  = t >> 3;
    int jj = t & 7;
    int j  = j0 + jj;
    g_hsplit[b * MEM + j]        = __float2bfloat16(0.0f);
    g_hsplit[(64 + b) * MEM + j] = __float2bfloat16(0.0f);
    float hreg = 0.0f;

    __syncthreads();
    CLUSTER_SYNC();

    unsigned int bar = 1;
    grid_barrier(bar);

    // warp GEMM role
    int m_tile = wid & 7;          // 16 rows at m_tile*16
    int n_half = wid >> 3;         // cols [n_half*16, +16)
    int rowgrp = m_tile >> 1;
    int base_off = ((m_tile & 1) * 16 + (lane & 15)) * 128 + ((lane >> 4) << 4);

    // first-step A fills
    if (t == 0) {
        FENCE_ASYNC_ALL();
        MBAR_EXPECT_TX(sb + OFF_FULL0, 65536);
#pragma unroll
        for (int s = 0; s < 4; s++)
            TMA_MC(sb + OFF_A + s * 16384 + rank * 4096, &tmap,
                   0 * 256 + s * 64, rank * 32, 0, sb + OFF_FULL0, 0xF);
        MBAR_EXPECT_TX(sb + OFF_FULL1, 65536);
#pragma unroll
        for (int s = 0; s < 4; s++)
            TMA_MC(sb + OFF_A + 65536 + s * 16384 + rank * 4096, &tmap,
                   1 * 256 + s * 64, rank * 32, 0, sb + OFF_FULL1, 0xF);
    }

    for (int l = 0; l < L_; l++) {
        size_t pb = (size_t)l * (3 * MEM) * B_;
        float ia = __ldg(&g_proj[pb + (size_t)j * B_ + b]);
        float ic = __ldg(&g_proj[pb + (size_t)(MEM + j) * B_ + b]);
        float io = __ldg(&g_proj[pb + (size_t)(2 * MEM + j) * B_ + b]);

        float dA[4] = {0.f, 0.f, 0.f, 0.f};
        float dB[4] = {0.f, 0.f, 0.f, 0.f};

#pragma unroll
        for (int c = 0; c < 4; c++) {
            uint32_t abuf = sb + OFF_A + (uint32_t)(c & 1) * 65536u + rowgrp * 4096u;
            // wait fill
            if (c == 0)      MBAR_WAIT(sb + OFF_FULL0, 0);
            else if (c == 1) MBAR_WAIT(sb + OFF_FULL1, 0);
            else if (c == 2) MBAR_WAIT(sb + OFF_FULL0, 1);
            else             MBAR_WAIT(sb + OFF_FULL1, 1);

#pragma unroll
            for (int kk = 0; kk < 16; kk++) {
                int off = base_off + ((kk & 3) << 5);
                uint32_t addr = abuf + (uint32_t)((kk >> 2) * 16384)
                              + (uint32_t)(off ^ ((off >> 3) & 0x70));
                uint32_t a0, a1, a2, a3;
                ldmatrix4(a0, a1, a2, a3, addr);
                int gk = c * 16 + kk;
                const uint2* wp = Wsm + (size_t)(gk * 4 + n_half * 2) * 32 + lane;
                uint2 bv0 = wp[0];
                uint2 bv1 = wp[32];
                mma16816(dA, a0, a1, a2, a3, bv0.x, bv0.y);
                mma16816(dB, a0, a1, a2, a3, bv1.x, bv1.y);
            }

            // refill consumed buffer with chunk c+2 of this step
            if (c < 2) {
                __syncthreads();
                if (t == 0) {
                    uint32_t dst = sb + OFF_A + (uint32_t)c * 65536u;
                    uint32_t fb  = sb + ((c == 0) ? OFF_FULL0 : OFF_FULL1);
                    MBAR_EXPECT_TX(fb, 65536);
#pragma unroll
                    for (int s = 0; s < 4; s++)
                        TMA_MC(dst + s * 16384 + rank * 4096, &tmap,
                               (c + 2) * 256 + s * 64, rank * 32, 0, fb, 0xF);
                }
            }
        }

        // epilogue: D frags -> Red
        __syncthreads();
        {
            int r0 = m_tile * 16 + (lane >> 2);
            int c0 = n_half * 16 + (lane & 3) * 2;
            RED[r0 * 33 + c0]           = dA[0];
            RED[r0 * 33 + c0 + 1]       = dA[1];
            RED[(r0 + 8) * 33 + c0]     = dA[2];
            RED[(r0 + 8) * 33 + c0 + 1] = dA[3];
            RED[r0 * 33 + c0 + 8]           = dB[0];
            RED[r0 * 33 + c0 + 9]           = dB[1];
            RED[(r0 + 8) * 33 + c0 + 8]     = dB[2];
            RED[(r0 + 8) * 33 + c0 + 9]     = dB[3];
        }
        __syncthreads();

        // combine: cols [a_hi 0-7 | c_hi 8-15 | a_lo 16-23 | c_lo 24-31], rows [hi 0-63 | lo 64-127]
        float ma = RED[b * 33 + jj]        + RED[b * 33 + 16 + jj]
                 + RED[(64 + b) * 33 + jj] + RED[(64 + b) * 33 + 16 + jj];
        float mc = RED[b * 33 + 8 + jj]        + RED[b * 33 + 24 + jj]
                 + RED[(64 + b) * 33 + 8 + jj] + RED[(64 + b) * 33 + 24 + jj];

        float a  = 1.0f + tanh_acc(ia + ma);
        float cg = sigmoid_acc(ic + mc);
        float hn = cg * hreg + (1.0f - cg) * tanh_acc(io + a * hreg);
        hreg = hn;

        __nv_bfloat16 hh = __float2bfloat16(hn);
        __nv_bfloat16 hl = __float2bfloat16(hn - __bfloat162float(hh));
        g_hsplit[b * MEM + j]        = hh;
        g_hsplit[(64 + b) * MEM + j] = hl;
        g_mem[(size_t)l * MEM * B_ + (size_t)j * B_ + b] = hn;

        grid_barrier(++bar);

        if (l < L_ - 1 && t == 0) {
            FENCE_ASYNC_ALL();
            MBAR_EXPECT_TX(sb + OFF_FULL0, 65536);
#pragma unroll
            for (int s = 0; s < 4; s++)
                TMA_MC(sb + OFF_A + s * 16384 + rank * 4096, &tmap,
                       0 * 256 + s * 64, rank * 32, 0, sb + OFF_FULL0, 0xF);
            MBAR_EXPECT_TX(sb + OFF_FULL1, 65536);
#pragma unroll
            for (int s = 0; s < 4; s++)
                TMA_MC(sb + OFF_A + 65536 + s * 16384 + rank * 4096, &tmap,
                       1 * 256 + s * 64, rank * 32, 0, sb + OFF_FULL1, 0xF);
        }
    }
    CLUSTER_SYNC();
}

// ---------------- K3: logits + softmax ----------------------------------------
__global__ void logits_kernel(const float* __restrict__ Wact,
                              const float* __restrict__ bact,
                              float* __restrict__ out) {
    __shared__ float Wa[MEM * DEC];
    int l = blockIdx.x;
    int b = threadIdx.x;
    for (int idx = b; idx < MEM * DEC; idx += B_) Wa[idx] = Wact[idx];
    __syncthreads();

    float a0 = bact[0], a1 = bact[1], a2 = bact[2];
    const float* mp = g_mem + (size_t)l * MEM * B_ + b;
#pragma unroll 8
    for (int k = 0; k < MEM; k++) {
        float v = mp[(size_t)k * B_];
        a0 += v * Wa[k * 3 + 0];
        a1 += v * Wa[k * 3 + 1];
        a2 += v * Wa[k * 3 + 2];
    }
    float m  = fmaxf(a0, fmaxf(a1, a2));
    float e0 = __expf(a0 - m), e1 = __expf(a1 - m), e2 = __expf(a2 - m);
    float inv = 1.0f / (e0 + e1 + e2);
    size_t ob = ((size_t)b * L_ + l) * DEC;
    out[ob + 0] = e0 * inv;
    out[ob + 1] = e1 * inv;
    out[ob + 2] = e2 * inv;
}

// ---------------- launch -------------------------------------------------------
typedef CUresult (*PFN_tmapEncode)(
    CUtensorMap*, CUtensorMapDataType, cuuint32_t, void*,
    const cuuint64_t*, const cuuint64_t*, const cuuint32_t*, const cuuint32_t*,
    CUtensorMapInterleave, CUtensorMapSwizzle, CUtensorMapL2promotion,
    CUtensorMapFloatOOBfill);

extern "C" void kernel_launch(void* const* d_in, const int* in_sizes, int n_in,
                              void* d_out, int out_size) {
    (void)in_sizes; (void)n_in; (void)out_size;
    const float* x   = (const float*)d_in[0];
    const float* Ws  = (const float*)d_in[1];
    const float* bs  = (const float*)d_in[2];
    const float* Wim = (const float*)d_in[3];
    const float* Wmm = (const float*)d_in[4];
    const float* Wac = (const float*)d_in[5];
    const float* bac = (const float*)d_in[6];
    float* out = (float*)d_out;

    // TMA descriptor for g_hsplit [rows=128][K=1024] bf16, box 64x32, SW128
    void* hs_ptr = nullptr;
    cudaGetSymbolAddress(&hs_ptr, g_hsplit);
    PFN_tmapEncode enc = nullptr;
    cudaDriverEntryPointQueryResult qr;
    cudaGetDriverEntryPoint("cuTensorMapEncodeTiled", (void**)&enc,
                            cudaEnableDefault, &qr);
    CUtensorMap tmap;
    {
        cuuint64_t dims[3]    = {MEM, 128, 1};
        cuuint64_t strides[2] = {MEM * 2, (cuuint64_t)MEM * 2 * 128};
        cuuint32_t box[3]     = {64, 32, 1};
        cuuint32_t es[3]      = {1, 1, 1};
        enc(&tmap, CU_TENSOR_MAP_DATA_TYPE_BFLOAT16, 3, hs_ptr,
            dims, strides, box, es,
            CU_TENSOR_MAP_INTERLEAVE_NONE, CU_TENSOR_MAP_SWIZZLE_128B,
            CU_TENSOR_MAP_L2_PROMOTION_L2_128B, CU_TENSOR_MAP_FLOAT_OOB_FILL_NONE);
    }

    cudaFuncSetAttribute(proj_kernel, cudaFuncAttributeMaxDynamicSharedMemorySize, 98304);
    cudaFuncSetAttribute(scan_tc,     cudaFuncAttributeMaxDynamicSharedMemorySize, SMEM_SCAN);

    reset_kernel<<<1, 1>>>();
    sense_kernel<<<B_ * L_, 128>>>(x, Ws, bs);
    proj_kernel<<<dim3(L_, 24), 256, 98304>>>(Wim);
    scan_tc<<<NCTA, NT, SMEM_SCAN>>>(Wmm, tmap);
    logits_kernel<<<L_, B_>>>(Wac, bac, out);
}

// round 5
// speedup vs baseline: 1.5148x; 1.0006x over previous
#include <cuda.h>
#include <cuda_runtime.h>
#include <cuda_bf16.h>
#include <math.h>
#include <stdint.h>

// Problem dims
#define B_    64
#define L_    1024
#define N_    64
#define INSZ  128
#define MEM   1024
#define DEC   3

#define NCTA  128
#define NT    512
#define JB    8

// ---------------- scratch ----------------------------------------------------
__device__ float g_inter[(size_t)L_ * B_ * INSZ];
__device__ float g_proj [(size_t)L_ * 3 * MEM * B_];          // [l][col][b]
__device__ __nv_bfloat16 g_hsplit[128 * MEM];                 // rows 0-63 hi, 64-127 lo
__device__ float g_mem  [(size_t)L_ * MEM * B_];              // [l][j][b]
__device__ unsigned int g_bar_count;
__device__ unsigned int g_bar_gen;

// ---------------- PTX helpers ------------------------------------------------
__device__ __forceinline__ uint32_t smem_u32(const void* p) {
    uint32_t a;
    asm("{ .reg .u64 t; cvta.to.shared.u64 t, %1; cvt.u32.u64 %0, t; }" : "=r"(a) : "l"(p));
    return a;
}
__device__ __forceinline__ uint32_t ctarank() {
    uint32_t r; asm("mov.u32 %0, %%cluster_ctarank;" : "=r"(r)); return r;
}

#define MBAR_INIT(a, c) asm volatile("mbarrier.init.shared.b64 [%0], %1;" :: "r"((uint32_t)(a)), "r"((uint32_t)(c)) : "memory")
#define MBAR_EXPECT_TX(a, n) asm volatile("mbarrier.arrive.expect_tx.shared.b64 _, [%0], %1;" :: "r"((uint32_t)(a)), "r"((uint32_t)(n)) : "memory")

#define MBAR_WAIT(a, par) do { \
    uint32_t _m = (uint32_t)(a); uint32_t _p = (uint32_t)(par); uint32_t _d; \
    asm volatile("{\n\t.reg .pred p;\n\t" \
        "mbarrier.try_wait.parity.acquire.cta.shared::cta.b64 p, [%1], %2;\n\t" \
        "selp.b32 %0, 1, 0, p;\n\t}" : "=r"(_d) : "r"(_m), "r"(_p) : "memory"); \
    if (!_d) { \
        asm volatile("{\n\t.reg .pred P1;\n\tWL_%=:\n\t" \
            "mbarrier.try_wait.parity.acquire.cta.shared::cta.b64 P1, [%0], %1, 0x989680;\n\t" \
            "@P1 bra.uni WD_%=;\n\tbra.uni WL_%=;\n\tWD_%=:\n\t}" \
            :: "r"(_m), "r"(_p) : "memory"); \
    } } while (0)

#define TMA_MC(dst, tm, cx, cy, cz, mbar, mask) \
    asm volatile("cp.async.bulk.tensor.3d.shared::cluster.global.tile.mbarrier::complete_tx::bytes.multicast::cluster " \
        "[%0], [%1, {%2, %3, %4}], [%5], %6;" \
        :: "r"((uint32_t)(dst)), "l"(tm), "r"((int32_t)(cx)), "r"((int32_t)(cy)), "r"((int32_t)(cz)), \
           "r"((uint32_t)(mbar)), "h"((uint16_t)(mask)) : "memory")

#define FENCE_ASYNC_ALL() asm volatile("fence.proxy.async;" ::: "memory")
#define CLUSTER_SYNC() do { \
    asm volatile("barrier.cluster.arrive.aligned;" ::: "memory"); \
    asm volatile("barrier.cluster.wait.aligned;" ::: "memory"); } while (0)

__device__ __forceinline__ void ldmatrix4(uint32_t& a0, uint32_t& a1, uint32_t& a2, uint32_t& a3,
                                          uint32_t addr) {
    asm volatile("ldmatrix.sync.aligned.m8n8.x4.shared.b16 {%0,%1,%2,%3}, [%4];"
        : "=r"(a0), "=r"(a1), "=r"(a2), "=r"(a3) : "r"(addr));
}
__device__ __forceinline__ void mma16816(float* d, uint32_t a0, uint32_t a1, uint32_t a2, uint32_t a3,
                                         uint32_t b0, uint32_t b1) {
    asm volatile("mma.sync.aligned.m16n8k16.row.col.f32.bf16.bf16.f32 "
        "{%0,%1,%2,%3}, {%4,%5,%6,%7}, {%8,%9}, {%0,%1,%2,%3};"
        : "+f"(d[0]), "+f"(d[1]), "+f"(d[2]), "+f"(d[3])
        : "r"(a0), "r"(a1), "r"(a2), "r"(a3), "r"(b0), "r"(b1));
}

// ---------------- activations ------------------------------------------------
__device__ __forceinline__ float tanh_acc(float x) {
    float ax = fabsf(x);
    float e  = __expf(-2.0f * ax);
    float t  = (1.0f - e) / (1.0f + e);
    return copysignf(t, x);
}
__device__ __forceinline__ float sigmoid_acc(float z) {
    return 1.0f / (1.0f + __expf(-z));
}
__device__ __forceinline__ uint32_t packbf(float x, float y, bool lo) {
    __nv_bfloat16 xh = __float2bfloat16(x), yh = __float2bfloat16(y);
    if (lo) {
        xh = __float2bfloat16(x - __bfloat162float(xh));
        yh = __float2bfloat16(y - __bfloat162float(yh));
    }
    return ((uint32_t)__bfloat16_as_ushort(yh) << 16) | (uint32_t)__bfloat16_as_ushort(xh);
}

// ---------------- reset -------------------------------------------------------
__global__ void reset_kernel() { g_bar_count = 0u; g_bar_gen = 0u; }

// ---------------- K1a: sense --------------------------------------------------
__global__ void sense_kernel(const float* __restrict__ x,
                             const float* __restrict__ Ws,
                             const float* __restrict__ bs) {
    __shared__ float xs[N_];
    int bl = blockIdx.x;
    int b  = bl >> 10;
    int l  = bl & (L_ - 1);
    int t  = threadIdx.x;
    if (t < N_) xs[t] = x[(size_t)bl * N_ + t];
    __syncthreads();
    float acc = bs[t];
#pragma unroll 16
    for (int n = 0; n < N_; n++) acc += xs[n] * Ws[n * INSZ + t];
    g_inter[((size_t)l * B_ + b) * INSZ + t] = acc;
}

// ---------------- K1b: proj ---------------------------------------------------
#define CB 128
__global__ void __launch_bounds__(256) proj_kernel(const float* __restrict__ Wim) {
    extern __shared__ float sm[];
    float* As = sm;
    float* Bs = sm + INSZ * B_;
    int l  = blockIdx.x;
    int cb = blockIdx.y;
    int t  = threadIdx.x;

    for (int idx = t; idx < B_ * INSZ; idx += 256) {
        int b = idx >> 7, k = idx & 127;
        As[k * B_ + b] = g_inter[((size_t)l * B_ + b) * INSZ + k];
    }
    for (int idx = t; idx < INSZ * CB; idx += 256) {
        int k = idx >> 7, cc = idx & 127;
        Bs[k * CB + cc] = Wim[(size_t)k * (3 * MEM) + cb * CB + cc];
    }
    __syncthreads();

    int cg = t >> 3;
    int bg = t & 7;
    float acc[4][8];
#pragma unroll
    for (int i = 0; i < 4; i++)
#pragma unroll
        for (int j = 0; j < 8; j++) acc[i][j] = 0.0f;

    for (int k = 0; k < INSZ; k++) {
        float4 bv  = *(const float4*)&Bs[k * CB + cg * 4];
        float4 a0  = *(const float4*)&As[k * B_ + bg * 8];
        float4 a1  = *(const float4*)&As[k * B_ + bg * 8 + 4];
        float bb[4] = {bv.x, bv.y, bv.z, bv.w};
        float aa[8] = {a0.x, a0.y, a0.z, a0.w, a1.x, a1.y, a1.z, a1.w};
#pragma unroll
        for (int i = 0; i < 4; i++)
#pragma unroll
            for (int j = 0; j < 8; j++) acc[i][j] += bb[i] * aa[j];
    }

    size_t base = (size_t)l * (3 * MEM) * B_ + (size_t)(cb * CB) * B_;
#pragma unroll
    for (int i = 0; i < 4; i++) {
        size_t rb = base + (size_t)(cg * 4 + i) * B_ + bg * 8;
        *(float4*)&g_proj[rb]     = make_float4(acc[i][0], acc[i][1], acc[i][2], acc[i][3]);
        *(float4*)&g_proj[rb + 4] = make_float4(acc[i][4], acc[i][5], acc[i][6], acc[i][7]);
    }
}

// ---------------- grid barrier -----------------------------------------------
__device__ __forceinline__ void grid_barrier(unsigned int target) {
    __syncthreads();
    if (threadIdx.x == 0) {
        __threadfence();
        unsigned int tk = atomicAdd(&g_bar_count, 1u);
        if (tk == NCTA - 1) {
            atomicExch(&g_bar_count, 0u);
            __threadfence();
            atomicAdd(&g_bar_gen, 1u);
        } else {
            while (*(volatile unsigned int*)&g_bar_gen < target) { }
            __threadfence();
        }
    }
    __syncthreads();
}

// ---------------- K2: mma.sync tensor-core scan --------------------------------
// smem: [0,1024) mbarriers; [1024,+64K) W frags; [66560,+128K) A bufs; Red 128x33
#define OFF_FULL0  0
#define OFF_FULL1  8
#define OFF_W      1024
#define OFF_A      (OFF_W + 65536)
#define OFF_RED    (OFF_A + 131072)
#define SMEM_SCAN  (OFF_RED + 128 * 33 * 4)

__global__ void __launch_bounds__(NT, 1) __cluster_dims__(4, 1, 1)
scan_tc(const float* __restrict__ Wmm, const __grid_constant__ CUtensorMap tmap) {
    extern __shared__ char smem[];
    uint32_t sb = smem_u32(smem);
    float* RED = (float*)(smem + OFF_RED);
    uint2* Wsm = (uint2*)(smem + OFF_W);
    int t    = threadIdx.x;
    int wid  = t >> 5, lane = t & 31;
    int j0   = blockIdx.x * JB;
    uint32_t rank = ctarank();

    if (t == 0) {
        MBAR_INIT(sb + OFF_FULL0, 1);
        MBAR_INIT(sb + OFF_FULL1, 1);
    }

    // ---- resident W fragments: Wsm[(gk*4 + nt)*32 + lane] = uint2{b0,b1}
    // n_local = nt*8 + lane/4; grp 0:a_hi 1:c_hi 2:a_lo 3:c_lo; k0 = gk*16 + (lane%4)*2
    for (int idx = t; idx < 64 * 4 * 32; idx += NT) {
        int ln = idx & 31, nt = (idx >> 5) & 3, gk = idx >> 7;
        int n_local = nt * 8 + (ln >> 2);
        int grp = n_local >> 3, jj = n_local & 7;
        int col = ((grp & 1) ? MEM : 0) + j0 + jj;
        bool lo = (grp >= 2);
        int k0 = gk * 16 + (ln & 3) * 2;
        float w0 = Wmm[(size_t)k0 * (2 * MEM) + col];
        float w1 = Wmm[(size_t)(k0 + 1) * (2 * MEM) + col];
        float w8 = Wmm[(size_t)(k0 + 8) * (2 * MEM) + col];
        float w9 = Wmm[(size_t)(k0 + 9) * (2 * MEM) + col];
        Wsm[idx] = make_uint2(packbf(w0, w1, lo), packbf(w8, w9, lo));
    }

    // ---- init h = 0
    int b  = t >> 3;
    int jj = t & 7;
    int j  = j0 + jj;
    g_hsplit[b * MEM + j]        = __float2bfloat16(0.0f);
    g_hsplit[(64 + b) * MEM + j] = __float2bfloat16(0.0f);
    float hreg = 0.0f;

    __syncthreads();
    CLUSTER_SYNC();

    unsigned int bar = 1;
    grid_barrier(bar);

    // warp GEMM role
    int m_tile = wid & 7;          // 16 rows at m_tile*16
    int n_half = wid >> 3;         // cols [n_half*16, +16)
    int rowgrp = m_tile >> 1;
    int base_off = ((m_tile & 1) * 16 + (lane & 15)) * 128 + ((lane >> 4) << 4);

    // first-step A fills
    if (t == 0) {
        FENCE_ASYNC_ALL();
        MBAR_EXPECT_TX(sb + OFF_FULL0, 65536);
#pragma unroll
        for (int s = 0; s < 4; s++)
            TMA_MC(sb + OFF_A + s * 16384 + rank * 4096, &tmap,
                   0 * 256 + s * 64, rank * 32, 0, sb + OFF_FULL0, 0xF);
        MBAR_EXPECT_TX(sb + OFF_FULL1, 65536);
#pragma unroll
        for (int s = 0; s < 4; s++)
            TMA_MC(sb + OFF_A + 65536 + s * 16384 + rank * 4096, &tmap,
                   1 * 256 + s * 64, rank * 32, 0, sb + OFF_FULL1, 0xF);
    }

    for (int l = 0; l < L_; l++) {
        size_t pb = (size_t)l * (3 * MEM) * B_;
        float ia = __ldg(&g_proj[pb + (size_t)j * B_ + b]);
        float ic = __ldg(&g_proj[pb + (size_t)(MEM + j) * B_ + b]);
        float io = __ldg(&g_proj[pb + (size_t)(2 * MEM + j) * B_ + b]);

        float dA[4] = {0.f, 0.f, 0.f, 0.f};
        float dB[4] = {0.f, 0.f, 0.f, 0.f};

#pragma unroll
        for (int c = 0; c < 4; c++) {
            uint32_t abuf = sb + OFF_A + (uint32_t)(c & 1) * 65536u + rowgrp * 4096u;
            // wait fill
            if (c == 0)      MBAR_WAIT(sb + OFF_FULL0, 0);
            else if (c == 1) MBAR_WAIT(sb + OFF_FULL1, 0);
            else if (c == 2) MBAR_WAIT(sb + OFF_FULL0, 1);
            else             MBAR_WAIT(sb + OFF_FULL1, 1);

#pragma unroll
            for (int kk = 0; kk < 16; kk++) {
                int off = base_off + ((kk & 3) << 5);
                uint32_t addr = abuf + (uint32_t)((kk >> 2) * 16384)
                              + (uint32_t)(off ^ ((off >> 3) & 0x70));
                uint32_t a0, a1, a2, a3;
                ldmatrix4(a0, a1, a2, a3, addr);
                int gk = c * 16 + kk;
                const uint2* wp = Wsm + (size_t)(gk * 4 + n_half * 2) * 32 + lane;
                uint2 bv0 = wp[0];
                uint2 bv1 = wp[32];
                mma16816(dA, a0, a1, a2, a3, bv0.x, bv0.y);
                mma16816(dB, a0, a1, a2, a3, bv1.x, bv1.y);
            }

            // refill consumed buffer with chunk c+2 of this step
            if (c < 2) {
                __syncthreads();
                if (t == 0) {
                    uint32_t dst = sb + OFF_A + (uint32_t)c * 65536u;
                    uint32_t fb  = sb + ((c == 0) ? OFF_FULL0 : OFF_FULL1);
                    MBAR_EXPECT_TX(fb, 65536);
#pragma unroll
                    for (int s = 0; s < 4; s++)
                        TMA_MC(dst + s * 16384 + rank * 4096, &tmap,
                               (c + 2) * 256 + s * 64, rank * 32, 0, fb, 0xF);
                }
            }
        }

        // epilogue: D frags -> Red
        __syncthreads();
        {
            int r0 = m_tile * 16 + (lane >> 2);
            int c0 = n_half * 16 + (lane & 3) * 2;
            RED[r0 * 33 + c0]           = dA[0];
            RED[r0 * 33 + c0 + 1]       = dA[1];
            RED[(r0 + 8) * 33 + c0]     = dA[2];
            RED[(r0 + 8) * 33 + c0 + 1] = dA[3];
            RED[r0 * 33 + c0 + 8]           = dB[0];
            RED[r0 * 33 + c0 + 9]           = dB[1];
            RED[(r0 + 8) * 33 + c0 + 8]     = dB[2];
            RED[(r0 + 8) * 33 + c0 + 9]     = dB[3];
        }
        __syncthreads();

        // combine: cols [a_hi 0-7 | c_hi 8-15 | a_lo 16-23 | c_lo 24-31], rows [hi 0-63 | lo 64-127]
        float ma = RED[b * 33 + jj]        + RED[b * 33 + 16 + jj]
                 + RED[(64 + b) * 33 + jj] + RED[(64 + b) * 33 + 16 + jj];
        float mc = RED[b * 33 + 8 + jj]        + RED[b * 33 + 24 + jj]
                 + RED[(64 + b) * 33 + 8 + jj] + RED[(64 + b) * 33 + 24 + jj];

        float a  = 1.0f + tanh_acc(ia + ma);
        float cg = sigmoid_acc(ic + mc);
        float hn = cg * hreg + (1.0f - cg) * tanh_acc(io + a * hreg);
        hreg = hn;

        __nv_bfloat16 hh = __float2bfloat16(hn);
        __nv_bfloat16 hl = __float2bfloat16(hn - __bfloat162float(hh));
        g_hsplit[b * MEM + j]        = hh;
        g_hsplit[(64 + b) * MEM + j] = hl;
        g_mem[(size_t)l * MEM * B_ + (size_t)j * B_ + b] = hn;

        grid_barrier(++bar);

        if (l < L_ - 1 && t == 0) {
            FENCE_ASYNC_ALL();
            MBAR_EXPECT_TX(sb + OFF_FULL0, 65536);
#pragma unroll
            for (int s = 0; s < 4; s++)
                TMA_MC(sb + OFF_A + s * 16384 + rank * 4096, &tmap,
                       0 * 256 + s * 64, rank * 32, 0, sb + OFF_FULL0, 0xF);
            MBAR_EXPECT_TX(sb + OFF_FULL1, 65536);
#pragma unroll
            for (int s = 0; s < 4; s++)
                TMA_MC(sb + OFF_A + 65536 + s * 16384 + rank * 4096, &tmap,
                       1 * 256 + s * 64, rank * 32, 0, sb + OFF_FULL1, 0xF);
        }
    }
    CLUSTER_SYNC();
}

// ---------------- K3: logits + softmax ----------------------------------------
__global__ void logits_kernel(const float* __restrict__ Wact,
                              const float* __restrict__ bact,
                              float* __restrict__ out) {
    __shared__ float Wa[MEM * DEC];
    int l = blockIdx.x;
    int b = threadIdx.x;
    for (int idx = b; idx < MEM * DEC; idx += B_) Wa[idx] = Wact[idx];
    __syncthreads();

    float a0 = bact[0], a1 = bact[1], a2 = bact[2];
    const float* mp = g_mem + (size_t)l * MEM * B_ + b;
#pragma unroll 8
    for (int k = 0; k < MEM; k++) {
        float v = mp[(size_t)k * B_];
        a0 += v * Wa[k * 3 + 0];
        a1 += v * Wa[k * 3 + 1];
        a2 += v * Wa[k * 3 + 2];
    }
    float m  = fmaxf(a0, fmaxf(a1, a2));
    float e0 = __expf(a0 - m), e1 = __expf(a1 - m), e2 = __expf(a2 - m);
    float inv = 1.0f / (e0 + e1 + e2);
    size_t ob = ((size_t)b * L_ + l) * DEC;
    out[ob + 0] = e0 * inv;
    out[ob + 1] = e1 * inv;
    out[ob + 2] = e2 * inv;
}

// ---------------- launch -------------------------------------------------------
typedef CUresult (*PFN_tmapEncode)(
    CUtensorMap*, CUtensorMapDataType, cuuint32_t, void*,
    const cuuint64_t*, const cuuint64_t*, const cuuint32_t*, const cuuint32_t*,
    CUtensorMapInterleave, CUtensorMapSwizzle, CUtensorMapL2promotion,
    CUtensorMapFloatOOBfill);

extern "C" void kernel_launch(void* const* d_in, const int* in_sizes, int n_in,
                              void* d_out, int out_size) {
    (void)in_sizes; (void)n_in; (void)out_size;
    const float* x   = (const float*)d_in[0];
    const float* Ws  = (const float*)d_in[1];
    const float* bs  = (const float*)d_in[2];
    const float* Wim = (const float*)d_in[3];
    const float* Wmm = (const float*)d_in[4];
    const float* Wac = (const float*)d_in[5];
    const float* bac = (const float*)d_in[6];
    float* out = (float*)d_out;

    // TMA descriptor for g_hsplit [rows=128][K=1024] bf16, box 64x32, SW128
    void* hs_ptr = nullptr;
    cudaGetSymbolAddress(&hs_ptr, g_hsplit);
    PFN_tmapEncode enc = nullptr;
    cudaDriverEntryPointQueryResult qr;
    cudaGetDriverEntryPoint("cuTensorMapEncodeTiled", (void**)&enc,
                            cudaEnableDefault, &qr);
    CUtensorMap tmap;
    {
        cuuint64_t dims[3]    = {MEM, 128, 1};
        cuuint64_t strides[2] = {MEM * 2, (cuuint64_t)MEM * 2 * 128};
        cuuint32_t box[3]     = {64, 32, 1};
        cuuint32_t es[3]      = {1, 1, 1};
        enc(&tmap, CU_TENSOR_MAP_DATA_TYPE_BFLOAT16, 3, hs_ptr,
            dims, strides, box, es,
            CU_TENSOR_MAP_INTERLEAVE_NONE, CU_TENSOR_MAP_SWIZZLE_128B,
            CU_TENSOR_MAP_L2_PROMOTION_L2_128B, CU_TENSOR_MAP_FLOAT_OOB_FILL_NONE);
    }

    cudaFuncSetAttribute(proj_kernel, cudaFuncAttributeMaxDynamicSharedMemorySize, 98304);
    cudaFuncSetAttribute(scan_tc,     cudaFuncAttributeMaxDynamicSharedMemorySize, SMEM_SCAN);

    reset_kernel<<<1, 1>>>();
    sense_kernel<<<B_ * L_, 128>>>(x, Ws, bs);
    proj_kernel<<<dim3(L_, 24), 256, 98304>>>(Wim);
    scan_tc<<<NCTA, NT, SMEM_SCAN>>>(Wmm, tmap);
    logits_kernel<<<L_, B_>>>(Wac, bac, out);
}